// round 1
// baseline (speedup 1.0000x reference)
#include <cuda_runtime.h>
#include <math.h>

typedef unsigned long long ull;

#define Bdim 8192
#define Ddim 64
#define Odim 256
#define BTILE 64
#define XS_STRIDE 66   // padded row stride (floats) for transposed x tile

// Scratch for projected centers: cproj[o][e] = sum_d betas[o][d][e] * centers[o][d]
__device__ float g_cproj[Odim * Ddim];

__global__ void cproj_kernel(const float* __restrict__ betas,
                             const float* __restrict__ centers) {
    int o = blockIdx.x;
    int e = threadIdx.x;
    const float* bo = betas + (size_t)o * Ddim * Ddim;
    const float* co = centers + (size_t)o * Ddim;
    float s = 0.f;
#pragma unroll 16
    for (int d = 0; d < Ddim; d++) s = fmaf(bo[d * Ddim + e], co[d], s);
    g_cproj[o * Ddim + e] = s;
}

__device__ __forceinline__ ull packdup(float v) {
    ull r;
    unsigned u = __float_as_uint(v);
    asm("mov.b64 %0, {%1, %1};" : "=l"(r) : "r"(u));
    return r;
}

__device__ __forceinline__ ull pack2(float a, float b) {
    ull r;
    asm("mov.b64 %0, {%1, %2};" : "=l"(r)
        : "r"(__float_as_uint(a)), "r"(__float_as_uint(b)));
    return r;
}

// packed dual-lane fp32 FMA: c.lo += a.lo*b.lo ; c.hi += a.hi*b.hi
__device__ __forceinline__ void ffma2(ull& c, ull a, ull b) {
    asm("fma.rn.f32x2 %0, %1, %2, %0;" : "+l"(c) : "l"(a), "l"(b));
}

// One block: one o, 64 consecutive b.  128 threads:
//   bt = tid&31  -> b pair (2*bt, 2*bt+1)
//   eg = tid>>5  -> e range [16*eg, 16*eg+16)   (whole warp shares eg -> betas LDS broadcast)
__global__ __launch_bounds__(128) void ebf_main(const float* __restrict__ x,
                                                const float* __restrict__ betas,
                                                float* __restrict__ out) {
    __shared__ __align__(16) float bs[Ddim * Ddim];        // betas[o], [d][e] layout
    __shared__ __align__(16) float xs[Ddim * XS_STRIDE];   // x tile transposed: [d][b_local]
    __shared__ float part[4][BTILE];

    int tid = threadIdx.x;
    int o = blockIdx.y;
    int b0 = blockIdx.x * BTILE;
    int bt = tid & 31;
    int eg = tid >> 5;

    // --- load betas[o] (coalesced float4) ---
    const float4* bg = (const float4*)(betas + (size_t)o * Ddim * Ddim);
    float4* bs4 = (float4*)bs;
#pragma unroll
    for (int i = 0; i < 8; i++) bs4[tid + i * 128] = bg[tid + i * 128];

    // --- load + transpose x tile (coalesced float4 read, padded smem write) ---
    const float4* xg = (const float4*)(x + (size_t)b0 * Ddim);
#pragma unroll
    for (int i = 0; i < 8; i++) {
        int idx4 = tid + i * 128;
        float4 v = xg[idx4];
        int bl = idx4 >> 4;           // local b row
        int d4 = (idx4 & 15) << 2;    // starting d
        xs[(d4 + 0) * XS_STRIDE + bl] = v.x;
        xs[(d4 + 1) * XS_STRIDE + bl] = v.y;
        xs[(d4 + 2) * XS_STRIDE + bl] = v.z;
        xs[(d4 + 3) * XS_STRIDE + bl] = v.w;
    }

    // --- init accumulators with cproj (y = cproj - sum beta*x) ---
    ull acc0[8], acc1[8];   // 8 e-pairs for b=2bt and b=2bt+1
    const float2* cp2 = (const float2*)(g_cproj + o * Ddim + eg * 16);
#pragma unroll
    for (int i = 0; i < 8; i++) {
        float2 c = cp2[i];
        ull cc = pack2(c.x, c.y);
        acc0[i] = cc;
        acc1[i] = cc;
    }
    __syncthreads();

    // --- main loop: 64 d iters, 16 FFMA2 each ---
#pragma unroll 4
    for (int d = 0; d < Ddim; d++) {
        float2 xv = *(const float2*)(xs + d * XS_STRIDE + 2 * bt);
        ull xa = packdup(-xv.x);
        ull xb = packdup(-xv.y);
        const ulonglong2* br = (const ulonglong2*)(bs + d * Ddim + eg * 16);
#pragma unroll
        for (int i = 0; i < 4; i++) {
            ulonglong2 p = br[i];   // 4 consecutive betas (2 f32x2 pairs), warp-broadcast
            ffma2(acc0[2 * i],     p.x, xa);
            ffma2(acc0[2 * i + 1], p.y, xa);
            ffma2(acc1[2 * i],     p.x, xb);
            ffma2(acc1[2 * i + 1], p.y, xb);
        }
    }

    // --- square-reduce own 16 e's per b ---
    float q0 = 0.f, q1 = 0.f;
#pragma unroll
    for (int i = 0; i < 8; i++) {
        float2 a = *(float2*)&acc0[i];
        q0 = fmaf(a.x, a.x, fmaf(a.y, a.y, q0));
        float2 b = *(float2*)&acc1[i];
        q1 = fmaf(b.x, b.x, fmaf(b.y, b.y, q1));
    }
    part[eg][2 * bt]     = q0;
    part[eg][2 * bt + 1] = q1;
    __syncthreads();

    // --- combine 4 e-groups, exp, store ---
    if (tid < BTILE) {
        float q = part[0][tid] + part[1][tid] + part[2][tid] + part[3][tid];
        out[(size_t)(b0 + tid) * Odim + o] = expf(-q);
    }
}

extern "C" void kernel_launch(void* const* d_in, const int* in_sizes, int n_in,
                              void* d_out, int out_size) {
    const float* x       = (const float*)d_in[0];   // [8192, 64]
    const float* centers = (const float*)d_in[1];   // [256, 1, 64]
    const float* betas   = (const float*)d_in[2];   // [256, 64, 64]
    float* out = (float*)d_out;                     // [8192, 256]

    cproj_kernel<<<Odim, Ddim>>>(betas, centers);
    dim3 grid(Bdim / BTILE, Odim);
    ebf_main<<<grid, 128>>>(x, betas, out);
}